// round 16
// baseline (speedup 1.0000x reference)
#include <cuda_runtime.h>
#include <cstdint>

// ---------------------------------------------------------------------------
// PoincareInputBlock: projx -> logmap0 -> conv3x3+bias -> exp/proj/log ->
// BN(batch stats) -> exp/proj/log -> relu -> expmap0+projx
// x:[16,3,224,224] f32, w:[3,3,3,64] HWIO, out:[16,224,224,64] f32
//
// R15: 8px x 8ch threads. Weight LDS amortized over 8 pixels (6.75/px),
// tile staged as duplicated float2 (LDS.64 -> packed reg, no movs),
// 8-deep ILP through the transcendental chains.
// ---------------------------------------------------------------------------

#define B_ 16
#define H_ 224
#define W_ 224
#define CIN 3
#define COUT 64
#define HWSZ (H_*W_)
#define NPIX (B_*H_*W_)          // 802816
#define TW 16                    // tile width (pixels)
#define TH 8                     // tile height
#define NBX (W_/TW)              // 14
#define NBY (H_/TH)              // 28
#define NBLK (NBX*NBY*B_)        // 6272

typedef unsigned long long u64;

__device__ float g_tlog[NPIX*CIN];          // tangent-space input, NHWC
__device__ float g_partials[128*NBLK];      // per-block sums(64) + sumsq(64)
__device__ float g_scale[COUT];
__device__ float g_shift[COUT];

// ---------------- packed f32x2 helpers -------------------------------------
__device__ __forceinline__ u64 mk64(unsigned lo, unsigned hi) {
    u64 r; asm("mov.b64 %0, {%1, %2};" : "=l"(r) : "r"(lo), "r"(hi)); return r;
}
__device__ __forceinline__ void sp64(u64 v, unsigned& lo, unsigned& hi) {
    asm("mov.b64 {%0, %1}, %2;" : "=r"(lo), "=r"(hi) : "l"(v));
}
__device__ __forceinline__ u64 pk(float a, float b) {
    return mk64(__float_as_uint(a), __float_as_uint(b));
}
__device__ __forceinline__ u64 pk2(float a) { return pk(a, a); }
__device__ __forceinline__ void upk(u64 v, float& a, float& b) {
    unsigned lo, hi; sp64(v, lo, hi);
    a = __uint_as_float(lo); b = __uint_as_float(hi);
}
__device__ __forceinline__ u64 pfma(u64 a, u64 b, u64 c) {
    u64 d;
    asm("fma.rn.f32x2 %0, %1, %2, %3;" : "=l"(d) : "l"(a), "l"(b), "l"(c));
    return d;
}
__device__ __forceinline__ u64 pmul(u64 a, u64 b) {
    u64 d;
    asm("mul.rn.f32x2 %0, %1, %2;" : "=l"(d) : "l"(a), "l"(b));
    return d;
}
__device__ __forceinline__ u64 padd(u64 a, u64 b) {
    u64 d;
    asm("add.rn.f32x2 %0, %1, %2;" : "=l"(d) : "l"(a), "l"(b));
    return d;
}
__device__ __forceinline__ u64 shfl64x(u64 v, int m) {
    unsigned lo, hi; sp64(v, lo, hi);
    lo = __shfl_xor_sync(0xffffffffu, lo, m);
    hi = __shfl_xor_sync(0xffffffffu, hi, m);
    return mk64(lo, hi);
}
// 4 pairs = 2x LDS.128 straight into u64 regs
__device__ __forceinline__ void ld4(const float* base, u64 w4[4]) {
    const ulonglong2* p = (const ulonglong2*)base;
    ulonglong2 a = p[0], b = p[1];
    w4[0] = a.x; w4[1] = a.y; w4[2] = b.x; w4[3] = b.y;
}

// ---------------- fast branchless Poincare chains ---------------------------
__device__ __forceinline__ float fchain_log_exp(float nsq) {
    float nu = sqrtf(nsq);
    float n1 = fmaxf(nu, 1e-7f);
    float E  = __expf(2.0f * n1);
    float th = 1.0f - __fdividef(2.0f, E + 1.0f);   // tanh(n1)
    float hp = fminf(th, nu);                       // = (th/n1)*nu exactly
    float sp = fminf(1.0f, __fdividef(0.999f, fmaxf(hp, 1e-7f)));
    float n3 = fmaxf(hp * sp, 1e-7f);
    float tt = fminf(n3, 0.99999f);
    float L  = 0.5f * __logf(__fdividef(1.0f + tt, 1.0f - tt));  // atanh(tt)
    return __fdividef(L * sp * th, n3 * n1);        // sl*sp*se
}
__device__ __forceinline__ float fchain_exp(float nsq) {
    float nu = sqrtf(nsq);
    float n1 = fmaxf(nu, 1e-7f);
    float E  = __expf(2.0f * n1);
    float th = 1.0f - __fdividef(2.0f, E + 1.0f);
    float hp = fminf(th, nu);
    float sp = fminf(1.0f, __fdividef(0.999f, fmaxf(hp, 1e-7f)));
    return __fdividef(th, n1) * sp;
}

// ---------------- robust scalar math (k0 only) ------------------------------
__device__ __forceinline__ float my_atanh(float t) {  // 0 <= t < 1
    if (t < 0.1f) {
        float t2 = t * t;
        return t * (1.0f + t2 * (0.33333334f + t2 * (0.2f + t2 * 0.14285715f)));
    }
    return 0.5f * logf((1.0f + t) / (1.0f - t));
}

// ---------------- K0: tangent-space input, 4px/thread, vector I/O -----------
__global__ void k0_tlog(const float* __restrict__ x) {
    int t   = blockIdx.x * 256 + threadIdx.x;        // NPIX/4 threads
    int idx = t * 4;
    int b   = idx / HWSZ;
    int hw  = idx - b * HWSZ;                        // multiple of 4
    const float* xb = x + b * (CIN * HWSZ);
    float4 a = *(const float4*)(xb + hw);
    float4 c = *(const float4*)(xb + HWSZ + hw);
    float4 d = *(const float4*)(xb + 2 * HWSZ + hw);
    float px[4][3] = {{a.x,c.x,d.x},{a.y,c.y,d.y},{a.z,c.z,d.z},{a.w,c.w,d.w}};
    float g[4];
#pragma unroll
    for (int p = 0; p < 4; ++p) {
        float nsq = px[p][0]*px[p][0] + px[p][1]*px[p][1] + px[p][2]*px[p][2];
        float nu = sqrtf(nsq);
        float n1 = fmaxf(nu, 1e-7f);
        float sp = fminf(1.0f, 0.999f / n1);
        float hn = nu * sp;
        float n3 = fmaxf(hn, 1e-7f);
        float tt = fminf(n3, 0.99999f);
        g[p] = sp * my_atanh(tt) / n3;
    }
    float* o = g_tlog + (size_t)idx * 3;             // 48B, 16B-aligned
    float4 o0 = make_float4(g[0]*px[0][0], g[0]*px[0][1], g[0]*px[0][2], g[1]*px[1][0]);
    float4 o1 = make_float4(g[1]*px[1][1], g[1]*px[1][2], g[2]*px[2][0], g[2]*px[2][1]);
    float4 o2 = make_float4(g[2]*px[2][2], g[3]*px[3][0], g[3]*px[3][1], g[3]*px[3][2]);
    ((float4*)o)[0] = o0; ((float4*)o)[1] = o1; ((float4*)o)[2] = o2;
}

// ---------------- shared staging -------------------------------------------
// sw2: weights [27 taps][8 cg][12 floats (8 used)]  (12-stride: bank-spread)
// st2: tile [10 rows][18 cols][3 ci] as DUPLICATED float2 (LDS.64 -> f32x2)
__device__ __forceinline__ void stage_common(
        const float* __restrict__ cw, float* sw2, float2* st2, int tid) {
    for (int i = tid; i < 1728; i += 128) {
        int tap = i >> 6, c = i & 63;
        sw2[tap * 96 + (c >> 3) * 12 + (c & 7)] = cw[i];
    }
    int x0 = blockIdx.x * TW, y0 = blockIdx.y * TH, b = blockIdx.z;
    for (int i = tid; i < 540; i += 128) {
        int r  = i / 54;
        int k  = i - r * 54;
        int c  = k / 3;
        int ci = k - 3 * c;
        int gh = y0 - 1 + r;
        int gw = x0 - 1 + c;
        float v = 0.0f;
        if ((unsigned)gh < (unsigned)H_ && (unsigned)gw < (unsigned)W_)
            v = g_tlog[((size_t)(b * H_ + gh) * W_ + gw) * 3 + ci];
        st2[i] = make_float2(v, v);
    }
}

// conv core: acc[p][i] = conv+bias, pixel row y0+p, pairs cg*4+i
__device__ __forceinline__ void conv8x4(const float2* st2, const float* sw2,
                                        const float* sbp, int cg, int xw,
                                        u64 acc[8][4]) {
    {
        u64 bb[4];
        ld4(sbp + cg * 12, bb);
#pragma unroll
        for (int p = 0; p < 8; ++p)
#pragma unroll
            for (int i = 0; i < 4; ++i) acc[p][i] = bb[i];
    }
    const u64* tp = (const u64*)st2;
#pragma unroll
    for (int dx = 0; dx < 3; ++dx)
#pragma unroll
        for (int ci = 0; ci < 3; ++ci) {
            u64 tv2[10];
#pragma unroll
            for (int r = 0; r < 10; ++r)
                tv2[r] = tp[(r * 18 + xw + dx) * 3 + ci];
#pragma unroll
            for (int dy = 0; dy < 3; ++dy) {
                u64 w4[4];
                ld4(sw2 + ((dy * 3 + dx) * 3 + ci) * 96 + cg * 12, w4);
#pragma unroll
                for (int p = 0; p < 8; ++p)
#pragma unroll
                    for (int i = 0; i < 4; ++i)
                        acc[p][i] = pfma(tv2[p + dy], w4[i], acc[p][i]);
            }
        }
}

// ---------------- K1: conv + f1 -> per-block channel stats ------------------
__global__ void __launch_bounds__(128, 4)
k1_stats(const float* __restrict__ cw, const float* __restrict__ cb) {
    __shared__ __align__(16) float sw2[27 * 96];
    __shared__ __align__(16) float sb2[96];
    __shared__ __align__(16) float2 st2[540];
    __shared__ u64 wsum[4][32], wqsum[4][32];

    int tid = threadIdx.x;
    int lane = tid & 31, w = tid >> 5;
    int xo = lane & 3, cg = lane >> 2;
    int xw = w * 4 + xo;

    stage_common(cw, sw2, st2, tid);
    if (tid < 64) sb2[(tid >> 3) * 12 + (tid & 7)] = cb[tid];
    __syncthreads();

    u64 acc[8][4];
    conv8x4(st2, sw2, sb2, cg, xw, acc);

    // all 8 squared norms (3-level shfl over cg bits), then 8 chains (ILP)
    float ns[8];
#pragma unroll
    for (int p = 0; p < 8; ++p) {
        u64 q2 = 0ull;
#pragma unroll
        for (int i = 0; i < 4; ++i) q2 = pfma(acc[p][i], acc[p][i], q2);
        float a, b; upk(q2, a, b);
        float v = a + b;
        v += __shfl_xor_sync(0xffffffffu, v, 4);
        v += __shfl_xor_sync(0xffffffffu, v, 8);
        v += __shfl_xor_sync(0xffffffffu, v, 16);
        ns[p] = v;
    }
    float f1v[8];
#pragma unroll
    for (int p = 0; p < 8; ++p) f1v[p] = fchain_log_exp(ns[p]);

    // u2 = f1*u; per-pair sum/sumsq over the 8 pixels
    u64 s[4], q[4];
#pragma unroll
    for (int i = 0; i < 4; ++i) { s[i] = 0ull; q[i] = 0ull; }
#pragma unroll
    for (int p = 0; p < 8; ++p) {
        u64 f1p = pk2(f1v[p]);
#pragma unroll
        for (int i = 0; i < 4; ++i) {
            u64 v = pmul(acc[p][i], f1p);
            s[i] = padd(s[i], v);
            q[i] = pfma(v, v, q[i]);
        }
    }
    // butterfly over xo bits (4 lanes share same cg)
#pragma unroll
    for (int m = 1; m <= 2; m <<= 1)
#pragma unroll
        for (int i = 0; i < 4; ++i) {
            s[i] = padd(s[i], shfl64x(s[i], m));
            q[i] = padd(q[i], shfl64x(q[i], m));
        }
    if (xo == 0)
#pragma unroll
        for (int i = 0; i < 4; ++i) {
            wsum[w][cg * 4 + i]  = s[i];
            wqsum[w][cg * 4 + i] = q[i];
        }
    __syncthreads();
    if (tid < 32) {
        u64 S = padd(padd(wsum[0][tid],  wsum[1][tid]),
                     padd(wsum[2][tid],  wsum[3][tid]));
        u64 Q = padd(padd(wqsum[0][tid], wqsum[1][tid]),
                     padd(wqsum[2][tid], wqsum[3][tid]));
        float s0, s1, q0, q1;
        upk(S, s0, s1); upk(Q, q0, q1);
        int blk = (blockIdx.z * NBY + blockIdx.y) * NBX + blockIdx.x;
        int c0 = ((tid >> 2) << 3) + ((tid & 3) << 1);   // pair j -> channel
        g_partials[c0 * NBLK + blk]              = s0;
        g_partials[(c0 + 1) * NBLK + blk]        = s1;
        g_partials[(64 + c0) * NBLK + blk]       = q0;
        g_partials[(64 + c0 + 1) * NBLK + blk]   = q1;
    }
}

// ---------------- K2: finalize BN scale/shift (deterministic) ---------------
__global__ void k2_finalize(const float* __restrict__ gamma,
                            const float* __restrict__ beta) {
    int c = blockIdx.x, tid = threadIdx.x;
    const float* ps = g_partials + (size_t)c * NBLK;
    const float* pq = g_partials + (size_t)(64 + c) * NBLK;
    float s = 0.0f, q = 0.0f;
    for (int i = tid; i < NBLK; i += 256) { s += ps[i]; q += pq[i]; }
    __shared__ float rs[256], rq[256];
    rs[tid] = s; rq[tid] = q;
    __syncthreads();
    for (int stp = 128; stp > 0; stp >>= 1) {
        if (tid < stp) { rs[tid] += rs[tid + stp]; rq[tid] += rq[tid + stp]; }
        __syncthreads();
    }
    if (tid == 0) {
        float inv  = 1.0f / (float)NPIX;
        float mean = rs[0] * inv;
        float var  = rq[0] * inv - mean * mean;
        float scl  = rsqrtf(var + 1e-5f) * gamma[c];
        g_scale[c] = scl;
        g_shift[c] = beta[c] - mean * scl;
    }
}

// ---------------- K3: recompute conv -> BN -> relu -> output ----------------
__global__ void __launch_bounds__(128, 4)
k3_output(const float* __restrict__ cw, const float* __restrict__ cb,
          float* __restrict__ out) {
    __shared__ __align__(16) float sw2[27 * 96];
    __shared__ __align__(16) float sb2[96];
    __shared__ __align__(16) float ssc[96];
    __shared__ __align__(16) float ssh[96];
    __shared__ __align__(16) float2 st2[540];

    int tid = threadIdx.x;
    int lane = tid & 31, w = tid >> 5;
    int xo = lane & 3, cg = lane >> 2;
    int xw = w * 4 + xo;

    stage_common(cw, sw2, st2, tid);
    if (tid < 64) {
        int d = (tid >> 3) * 12 + (tid & 7);
        sb2[d] = cb[tid];
        ssc[d] = g_scale[tid];
        ssh[d] = g_shift[tid];
    }
    __syncthreads();

    u64 acc[8][4];
    conv8x4(st2, sw2, sb2, cg, xw, acc);

    // stage 1: 8 norms, then 8 f1 chains (ILP)
    float ns[8];
#pragma unroll
    for (int p = 0; p < 8; ++p) {
        u64 q2 = 0ull;
#pragma unroll
        for (int i = 0; i < 4; ++i) q2 = pfma(acc[p][i], acc[p][i], q2);
        float a, b; upk(q2, a, b);
        float v = a + b;
        v += __shfl_xor_sync(0xffffffffu, v, 4);
        v += __shfl_xor_sync(0xffffffffu, v, 8);
        v += __shfl_xor_sync(0xffffffffu, v, 16);
        ns[p] = v;
    }
    float f1v[8];
#pragma unroll
    for (int p = 0; p < 8; ++p) f1v[p] = fchain_log_exp(ns[p]);

    // stage 2: u3 = (f1*u)*scale + shift; ns2 = ||u3||^2;
    //          srel = ||relu(u3)||^2 (relu mask f2-invariant); acc <- relu(u3)
    u64 scp[4], shp[4];
    ld4(ssc + cg * 12, scp);
    ld4(ssh + cg * 12, shp);
    float ns2[8], srel[8];
#pragma unroll
    for (int p = 0; p < 8; ++p) {
        u64 f1p = pk2(f1v[p]);
        u64 n2 = 0ull;
        float sr = 0.0f;
#pragma unroll
        for (int i = 0; i < 4; ++i) {
            u64 u3 = pfma(acc[p][i], pmul(f1p, scp[i]), shp[i]);
            n2 = pfma(u3, u3, n2);
            float a, b; upk(u3, a, b);
            a = fmaxf(a, 0.0f); b = fmaxf(b, 0.0f);
            sr = fmaf(a, a, sr); sr = fmaf(b, b, sr);
            acc[p][i] = pk(a, b);
        }
        float a, b; upk(n2, a, b);
        float v = a + b;
        v  += __shfl_xor_sync(0xffffffffu, v, 4);
        v  += __shfl_xor_sync(0xffffffffu, v, 8);
        v  += __shfl_xor_sync(0xffffffffu, v, 16);
        sr += __shfl_xor_sync(0xffffffffu, sr, 4);
        sr += __shfl_xor_sync(0xffffffffu, sr, 8);
        sr += __shfl_xor_sync(0xffffffffu, sr, 16);
        ns2[p] = v; srel[p] = sr;
    }

    // stage 3: f2 chains x8 (ILP), then fused f3 scale x8
    float f2v[8];
#pragma unroll
    for (int p = 0; p < 8; ++p) f2v[p] = fchain_log_exp(ns2[p]);
    float sf[8];
#pragma unroll
    for (int p = 0; p < 8; ++p) {
        float f3 = fchain_exp(f2v[p] * f2v[p] * srel[p]);
        sf[p] = f2v[p] * f3;
    }

    // stage 4: scaled stores, 2x STG.128 per pixel (warp covers 1KB rows)
    int x0 = blockIdx.x * TW, y0 = blockIdx.y * TH, b = blockIdx.z;
#pragma unroll
    for (int p = 0; p < 8; ++p) {
        u64 sfp = pk2(sf[p]);
        float* po = out + ((size_t)(b * H_ + y0 + p) * W_ + x0 + xw) * COUT + cg * 8;
        ulonglong2* pv = (ulonglong2*)po;
        ulonglong2 v0, v1;
        v0.x = pmul(acc[p][0], sfp); v0.y = pmul(acc[p][1], sfp);
        v1.x = pmul(acc[p][2], sfp); v1.y = pmul(acc[p][3], sfp);
        pv[0] = v0; pv[1] = v1;
    }
}

// ---------------- launch -----------------------------------------------------
extern "C" void kernel_launch(void* const* d_in, const int* in_sizes, int n_in,
                              void* d_out, int out_size) {
    const float* x  = (const float*)d_in[0];
    const float* cw = (const float*)d_in[1];
    const float* cb = (const float*)d_in[2];
    const float* gm = (const float*)d_in[3];
    const float* bt = (const float*)d_in[4];
    float* out = (float*)d_out;

    k0_tlog<<<NPIX / 4 / 256, 256>>>(x);
    dim3 grid(NBX, NBY, B_), blk(128);
    k1_stats<<<grid, blk>>>(cw, cb);
    k2_finalize<<<COUT, 256>>>(gm, bt);
    k3_output<<<grid, blk>>>(cw, cb, out);
}